// round 16
// baseline (speedup 1.0000x reference)
#include <cuda_runtime.h>
#include <cuda_bf16.h>
#include <cstdint>

#define BATCH   16384
#define IN_SIZE 4096
#define NPART   8
#define DDIM    512

#define BM 128
#define BN 128
#define BK 64
#define THREADS 256
#define NCHUNK (DDIM / BK)       // 8
#define STAGES 3

#define TILE_BYTES   16384       // one 16KB operand tile (A: 128x64 bf16, B: 64x128 bf16)
#define STAGE_BYTES  (2 * TILE_BYTES)
#define SMEM_STAGE0  1024
#define SMEM_TOTAL   (SMEM_STAGE0 + STAGES * STAGE_BYTES)   // 99328

// Device-global scratch (allocation APIs forbidden).
// xb/midb: tile-major swizzled bf16 activations. A-tile index = (mt*8+p)*8+kc
// w1b/w2b: tile-major swizzled bf16 weights.     B-tile index = (p*4+nt)*8+kc
__device__ __align__(16) __nv_bfloat16 g_xb  [(size_t)BATCH * IN_SIZE];
__device__ __align__(16) __nv_bfloat16 g_midb[(size_t)BATCH * IN_SIZE];
__device__ __align__(16) __nv_bfloat16 g_w1b [(size_t)NPART * DDIM * DDIM];
__device__ __align__(16) __nv_bfloat16 g_w2b [(size_t)NPART * DDIM * DDIM];
__device__ float g_beff1[IN_SIZE];
__device__ float g_beff2[IN_SIZE];

// ---------------------------------------------------------------------------
#define MBARRIER_INIT(addr, cnt) \
    asm volatile("mbarrier.init.shared.b64 [%0], %1;" :: "r"(addr), "r"(cnt) : "memory")
#define MBARRIER_EXPECT_TX(addr, bytes) \
    asm volatile("mbarrier.arrive.expect_tx.shared.b64 _, [%0], %1;" \
                 :: "r"(addr), "r"(bytes) : "memory")
#define MBARRIER_ARRIVE(addr) \
    asm volatile("mbarrier.arrive.shared.b64 _, [%0];" :: "r"(addr) : "memory")
#define MBARRIER_WAIT_PARITY(mbar, par) do {                                   \
    uint32_t _m = (mbar); uint32_t _p = (par); uint32_t _done;                 \
    asm volatile("{\n\t.reg .pred p;\n\t"                                      \
        "mbarrier.try_wait.parity.acquire.cta.shared::cta.b64 p, [%1], %2;\n\t"\
        "selp.b32 %0, 1, 0, p;\n\t}"                                           \
        : "=r"(_done) : "r"(_m), "r"(_p) : "memory");                          \
    if (!_done) {                                                              \
        asm volatile("{\n\t.reg .pred P1;\n\t"                                 \
            "WAIT_LOOP_%=:\n\t"                                                \
            "mbarrier.try_wait.parity.acquire.cta.shared::cta.b64 P1, [%0], %1, 0x989680;\n\t" \
            "@P1 bra.uni WAIT_DONE_%=;\n\t"                                    \
            "bra.uni WAIT_LOOP_%=;\n\t"                                        \
            "WAIT_DONE_%=:\n\t}"                                               \
            :: "r"(_m), "r"(_p) : "memory");                                   \
    }                                                                          \
} while (0)

// Bulk async copies (UBLKCP). sm_90 baseline PTX (not 'a'-gated).
#define CP_BULK_G2S(dst, src, bytes, mbar) \
    asm volatile("cp.async.bulk.shared::cluster.global.mbarrier::complete_tx::bytes " \
                 "[%0], [%1], %2, [%3];" \
                 :: "r"(dst), "l"(src), "r"(bytes), "r"(mbar) : "memory")
#define CP_BULK_S2G(dst, src, bytes) \
    asm volatile("cp.async.bulk.global.shared::cta.bulk_group [%0], [%1], %2;" \
                 :: "l"(dst), "r"(src), "r"(bytes) : "memory")
#define CP_BULK_COMMIT() asm volatile("cp.async.bulk.commit_group;" ::: "memory")
#define CP_BULK_WAIT0()  asm volatile("cp.async.bulk.wait_group 0;" ::: "memory")

__device__ __forceinline__ void ldsm_x4(uint32_t* r, uint32_t addr) {
    asm volatile("ldmatrix.sync.aligned.m8n8.x4.shared.b16 {%0,%1,%2,%3}, [%4];"
                 : "=r"(r[0]), "=r"(r[1]), "=r"(r[2]), "=r"(r[3]) : "r"(addr));
}
__device__ __forceinline__ void ldsm_x4_t(uint32_t* r, uint32_t addr) {
    asm volatile("ldmatrix.sync.aligned.m8n8.x4.trans.shared.b16 {%0,%1,%2,%3}, [%4];"
                 : "=r"(r[0]), "=r"(r[1]), "=r"(r[2]), "=r"(r[3]) : "r"(addr));
}
__device__ __forceinline__ void mma_bf16(float c[4], const uint32_t a[4],
                                         uint32_t b0, uint32_t b1) {
    asm volatile(
        "mma.sync.aligned.m16n8k16.row.col.f32.bf16.bf16.f32 "
        "{%0,%1,%2,%3}, {%4,%5,%6,%7}, {%8,%9}, {%0,%1,%2,%3};"
        : "+f"(c[0]), "+f"(c[1]), "+f"(c[2]), "+f"(c[3])
        : "r"(a[0]), "r"(a[1]), "r"(a[2]), "r"(a[3]), "r"(b0), "r"(b1));
}

// ---------------------------------------------------------------------------
// bias_eff[col] = bias[col] + nb * colsum(W)[col]  — coalesced.
__global__ void beff_kernel(const float* __restrict__ W,
                            const float* __restrict__ bias,
                            const float* __restrict__ nb,
                            float* __restrict__ beff) {
    __shared__ float part[4][256];
    const int p    = blockIdx.x >> 1;
    const int half = blockIdx.x & 1;
    const int c    = threadIdx.x & 255;
    const int ks   = threadIdx.x >> 8;
    const int col  = half * 256 + c;

    const float* Wp = W + (size_t)p * DDIM * DDIM + col;
    float sum = 0.f;
    const int k0 = ks * 128;
    #pragma unroll 8
    for (int k = k0; k < k0 + 128; k++) sum += Wp[(size_t)k * DDIM];
    part[ks][c] = sum;
    __syncthreads();
    if (ks == 0) {
        float s = part[0][c] + part[1][c] + part[2][c] + part[3][c];
        beff[p * DDIM + col] = bias[p * DDIM + col] + nb[0] * s;
    }
}

// W * gain -> bf16, tiled+swizzled. B tile for (p,nt,kc): 64 K-rows x 128 N-cols,
// stored as two 64x64 halves; off = h*8192 + kk*128 + ((nn*2) ^ ((kk&7)*16)).
__global__ void convw_kernel(const float* __restrict__ W,
                             const float* __restrict__ gain_p,
                             __nv_bfloat16* __restrict__ Wb) {
    const float gain = gain_p[0];
    int gid = blockIdx.x * blockDim.x + threadIdx.x;   // 8 elems each
    int n0  = (gid & 63) * 8;
    int k   = (gid >> 6) & 511;
    int p   = gid >> 15;

    const float* src = W + ((size_t)p * DDIM + k) * DDIM + n0;
    float4 v0 = *reinterpret_cast<const float4*>(src);
    float4 v1 = *reinterpret_cast<const float4*>(src + 4);
    __nv_bfloat162 o[4];
    o[0] = __floats2bfloat162_rn(v0.x * gain, v0.y * gain);
    o[1] = __floats2bfloat162_rn(v0.z * gain, v0.w * gain);
    o[2] = __floats2bfloat162_rn(v1.x * gain, v1.y * gain);
    o[3] = __floats2bfloat162_rn(v1.z * gain, v1.w * gain);

    int kc = k >> 6, kk = k & 63;
    int nt = n0 >> 7, h = (n0 >> 6) & 1, nn = n0 & 63;
    size_t tile = ((size_t)(p * 4 + nt) * NCHUNK + kc) * TILE_BYTES;
    uint32_t off = h * 8192 + kk * 128 + (uint32_t)((nn * 2) ^ ((kk & 7) * 16));
    *reinterpret_cast<uint4*>(reinterpret_cast<char*>(Wb) + tile + off) =
        *reinterpret_cast<uint4*>(o);
}

// x -> bf16, tiled+swizzled A tiles.
__global__ void convx_kernel(const float* __restrict__ X,
                             __nv_bfloat16* __restrict__ Xb) {
    int gid = blockIdx.x * blockDim.x + threadIdx.x;
    int c0  = (gid & 63) * 8;
    int prow = gid >> 6;
    int p   = prow & 7;
    int row = prow >> 3;

    const float* src = X + (size_t)row * IN_SIZE + p * DDIM + c0;
    float4 v0 = *reinterpret_cast<const float4*>(src);
    float4 v1 = *reinterpret_cast<const float4*>(src + 4);
    __nv_bfloat162 o[4];
    o[0] = __floats2bfloat162_rn(v0.x, v0.y);
    o[1] = __floats2bfloat162_rn(v0.z, v0.w);
    o[2] = __floats2bfloat162_rn(v1.x, v1.y);
    o[3] = __floats2bfloat162_rn(v1.z, v1.w);

    int mt = row >> 7, r = row & 127;
    int kc = c0 >> 6, c = c0 & 63;
    size_t tile = ((size_t)(mt * NPART + p) * NCHUNK + kc) * TILE_BYTES;
    uint32_t off = r * 128 + (uint32_t)((c * 2) ^ ((r & 7) * 16));
    *reinterpret_cast<uint4*>(reinterpret_cast<char*>(Xb) + tile + off) =
        *reinterpret_cast<uint4*>(o);
}

// ---------------------------------------------------------------------------
// One layer GEMM: Out = swish( A @ W_eff_p + beff, gamma, beta ) [+ X residual]
// Warp-decoupled 3-stage pipeline, producer at bottom (R14-proven mainloop).
// SECOND=false: epilogue stages mid tile in smem and emits it via bulk S2G.
template <bool SECOND>
__global__ __launch_bounds__(THREADS, 2)
void bt_gemm(const float* __restrict__ X,
             const __nv_bfloat16* __restrict__ Ain,   // tiled (xb or midb)
             const __nv_bfloat16* __restrict__ Wb,    // tiled weights
             const float* __restrict__ beff,
             const float* __restrict__ gamma,
             const float* __restrict__ beta,
             float* __restrict__ Out,
             __nv_bfloat16* __restrict__ MidOut) {    // tiled (layer1 output)
    extern __shared__ char smem[];
    const uint32_t sb = (uint32_t)__cvta_generic_to_shared(smem);

    const int tid  = threadIdx.x;
    const int warp = tid >> 5;
    const int lane = tid & 31;

    const int ng = blockIdx.x;            // 0..31  (partition*4 + n-tile)
    const int mt = blockIdx.y;            // 0..127
    const int p  = ng >> 2;
    const int nt = ng & 3;

    const int row0  = mt * BM;
    const int gcol0 = p * DDIM + nt * BN;

    // full[s] at sb + 8*s ; empty[s] at sb + 24 + 8*s
    if (tid == 0) {
        MBARRIER_INIT(sb + 0, 1);
        MBARRIER_INIT(sb + 8, 1);
        MBARRIER_INIT(sb + 16, 1);
        MBARRIER_INIT(sb + 24, 8);
        MBARRIER_INIT(sb + 32, 8);
        MBARRIER_INIT(sb + 40, 8);
    }
    __syncthreads();

    const char* Abase = reinterpret_cast<const char*>(Ain) +
                        ((size_t)(mt * NPART + p) * NCHUNK) * TILE_BYTES;
    const char* Bbase = reinterpret_cast<const char*>(Wb) +
                        ((size_t)(p * 4 + nt) * NCHUNK) * TILE_BYTES;

    auto issue = [&](int s, int kc) {
        uint32_t mb = sb + 8 * s;
        uint32_t a_st = sb + SMEM_STAGE0 + s * STAGE_BYTES;
        MBARRIER_EXPECT_TX(mb, STAGE_BYTES);
        CP_BULK_G2S(a_st, Abase + (size_t)kc * TILE_BYTES, TILE_BYTES, mb);
        CP_BULK_G2S(a_st + TILE_BYTES, Bbase + (size_t)kc * TILE_BYTES, TILE_BYTES, mb);
    };

    // Prologue: all 3 stages in flight.
    if (tid == 0) { issue(0, 0); issue(1, 1); issue(2, 2); }

    // Warp layout: 4 (M) x 2 (N); warp tile 32x64
    const int wm = (warp >> 1) * 32;
    const int wn = (warp & 1) * 64;
    const int bh = wn >> 6;

    const int a_row = wm + (lane & 15);
    const int a_cb  = (lane >> 4) * 16;
    const int b_row = lane & 15;
    const int b_nb  = (lane >> 4) * 16;

    float acc[2][8][4];
    #pragma unroll
    for (int i = 0; i < 2; i++)
        #pragma unroll
        for (int j = 0; j < 8; j++)
            #pragma unroll
            for (int k = 0; k < 4; k++) acc[i][j][k] = 0.0f;

    uint32_t af[2][2][4];   // [kk-parity][im][frag]
    uint32_t bb[2][4];      // [np-parity][frag]

    #pragma unroll
    for (int kc = 0; kc < NCHUNK; kc++) {
        const int s = kc % STAGES;

        MBARRIER_WAIT_PARITY(sb + 8 * s, (kc / 3) & 1);

        const uint32_t a_st = sb + SMEM_STAGE0 + s * STAGE_BYTES;
        const uint32_t b_st = a_st + TILE_BYTES + bh * 8192;

        auto a_addr = [&](int kk, int im) -> uint32_t {
            int r = a_row + im * 16;
            return a_st + r * 128 + (uint32_t)((kk * 2 + a_cb) ^ ((r & 7) * 16));
        };
        auto b_addr = [&](int kk, int np) -> uint32_t {
            int r = kk + b_row;
            return b_st + r * 128 + (uint32_t)((np * 32 + b_nb) ^ ((r & 7) * 16));
        };

        ldsm_x4(af[0][0], a_addr(0, 0));
        ldsm_x4(af[0][1], a_addr(0, 1));
        ldsm_x4_t(bb[0], b_addr(0, 0));

        #pragma unroll
        for (int ki = 0; ki < 4; ki++) {
            const int kk = ki * 16;
            const int pa = ki & 1;
            #pragma unroll
            for (int np = 0; np < 4; np++) {
                const int cb = np & 1;
                if (np < 3) {
                    ldsm_x4_t(bb[cb ^ 1], b_addr(kk, np + 1));
                } else if (ki < 3) {
                    ldsm_x4_t(bb[cb ^ 1], b_addr(kk + 16, 0));
                    ldsm_x4(af[pa ^ 1][0], a_addr(kk + 16, 0));
                    ldsm_x4(af[pa ^ 1][1], a_addr(kk + 16, 1));
                }
                mma_bf16(acc[0][np * 2 + 0], af[pa][0], bb[cb][0], bb[cb][1]);
                mma_bf16(acc[0][np * 2 + 1], af[pa][0], bb[cb][2], bb[cb][3]);
                mma_bf16(acc[1][np * 2 + 0], af[pa][1], bb[cb][0], bb[cb][1]);
                mma_bf16(acc[1][np * 2 + 1], af[pa][1], bb[cb][2], bb[cb][3]);
            }
        }

        // Consumer arrival: this warp is done reading stage s.
        if (kc + STAGES < NCHUNK && lane == 0) MBARRIER_ARRIVE(sb + 24 + 8 * s);

        // Producer (bottom): reissue this stage for chunk kc+3 once all 8
        // warps drained chunk kc (warp 0 already arrived above).
        if (tid == 0 && kc + STAGES < NCHUNK) {
            MBARRIER_WAIT_PARITY(sb + 24 + 8 * s, (kc / 3) & 1);
            issue(s, kc + STAGES);
        }
    }

    // ---- stage swish params in smem (stage 2 region is dead after sync;
    //      stages 0-1 are reused below for the mid-tile staging)
    __syncthreads();
    float* sP = reinterpret_cast<float*>(smem + SMEM_STAGE0 + 2 * STAGE_BYTES);
    if (tid < 128) {
        sP[tid]       = beff[gcol0 + tid];
        sP[128 + tid] = gamma[gcol0 + tid];
        sP[256 + tid] = beta[gcol0 + tid];
    }
    __syncthreads();

    // ---- epilogue: v = acc + beff; parametric swish; (+residual)
    const int g  = lane >> 2;
    const int t2 = (lane & 3) << 1;
    #pragma unroll
    for (int im = 0; im < 2; im++) {
        #pragma unroll
        for (int n_ = 0; n_ < 8; n_++) {
            const int lr0 = wm + im * 16 + g;           // local row 0..127
            const int ci  = wn + n_ * 8 + t2;           // 0..127
            const float be0 = sP[ci],       be1 = sP[ci + 1];
            const float gm0 = sP[128 + ci], gm1 = sP[128 + ci + 1];
            const float bt0 = sP[256 + ci], bt1 = sP[256 + ci + 1];
            #pragma unroll
            for (int h = 0; h < 2; h++) {
                const int lr = lr0 + h * 8;
                float v0 = acc[im][n_][h * 2 + 0] + be0;
                float v1 = acc[im][n_][h * 2 + 1] + be1;
                const float s0 = 1.0f / (1.0f + __expf(-bt0 * v0));
                const float s1 = 1.0f / (1.0f + __expf(-bt1 * v1));
                float o0 = (gm0 + s0 * (1.0f - gm0)) * v0;
                float o1 = (gm1 + s1 * (1.0f - gm1)) * v1;
                if (SECOND) {
                    const int rg  = row0 + lr;
                    const int col = gcol0 + ci;
                    const float2 rx = *reinterpret_cast<const float2*>(
                        &X[(size_t)rg * IN_SIZE + col]);
                    *reinterpret_cast<float2*>(&Out[(size_t)rg * IN_SIZE + col]) =
                        make_float2(o0 + rx.x, o1 + rx.y);
                } else {
                    // Stage mid tile in smem (A-tile format); bank-conflict-free
                    // (8 row-groups x 4 banks, XOR covers all 32 banks once).
                    const int lt = ci >> 6;             // local tile 0/1
                    const int cc = ci & 63;
                    uint32_t off = (uint32_t)(SMEM_STAGE0 + lt * TILE_BYTES +
                                   lr * 128 + ((cc * 2) ^ ((lr & 7) * 16)));
                    *reinterpret_cast<__nv_bfloat162*>(smem + off) =
                        __floats2bfloat162_rn(o0, o1);
                }
            }
        }
    }

    if (!SECOND) {
        __syncthreads();
        if (tid == 0) {
            asm volatile("fence.proxy.async;" ::: "memory");
            char* dst0 = reinterpret_cast<char*>(MidOut) +
                         ((size_t)(mt * NPART + p) * NCHUNK + nt * 2) * TILE_BYTES;
            CP_BULK_S2G(dst0, sb + SMEM_STAGE0, TILE_BYTES);
            CP_BULK_S2G(dst0 + TILE_BYTES, sb + SMEM_STAGE0 + TILE_BYTES, TILE_BYTES);
            CP_BULK_COMMIT();
            CP_BULK_WAIT0();
        }
    }
}

// ---------------------------------------------------------------------------
extern "C" void kernel_launch(void* const* d_in, const int* in_sizes, int n_in,
                              void* d_out, int out_size) {
    (void)in_sizes; (void)n_in; (void)out_size;
    const float* x      = (const float*)d_in[0];
    const float* w1     = (const float*)d_in[1];
    const float* b1     = (const float*)d_in[2];
    const float* w2     = (const float*)d_in[3];
    const float* b2     = (const float*)d_in[4];
    const float* gamma1 = (const float*)d_in[5];
    const float* beta1  = (const float*)d_in[6];
    const float* gamma3 = (const float*)d_in[7];
    const float* beta3  = (const float*)d_in[8];
    const float* gain1  = (const float*)d_in[9];
    const float* nbias1 = (const float*)d_in[10];
    const float* gain3  = (const float*)d_in[11];
    const float* nbias3 = (const float*)d_in[12];
    float* out = (float*)d_out;

    __nv_bfloat16 *xb, *midb, *w1b, *w2b;
    float *beff1, *beff2;
    cudaGetSymbolAddress((void**)&xb,    g_xb);
    cudaGetSymbolAddress((void**)&midb,  g_midb);
    cudaGetSymbolAddress((void**)&w1b,   g_w1b);
    cudaGetSymbolAddress((void**)&w2b,   g_w2b);
    cudaGetSymbolAddress((void**)&beff1, g_beff1);
    cudaGetSymbolAddress((void**)&beff2, g_beff2);

    cudaFuncSetAttribute(bt_gemm<false>,
                         cudaFuncAttributeMaxDynamicSharedMemorySize, SMEM_TOTAL);
    cudaFuncSetAttribute(bt_gemm<true>,
                         cudaFuncAttributeMaxDynamicSharedMemorySize, SMEM_TOTAL);

    dim3 grid(32, 128);
    dim3 block(THREADS);

    // Order: gemm1 is the 4th launch (the one ncu captures).
    convx_kernel<<<32768, 256>>>(x, xb);
    convw_kernel<<<1024, 256>>>(w1, gain1, w1b);
    beff_kernel<<<16, 1024>>>(w1, b1, nbias1, beff1);
    bt_gemm<false><<<grid, block, SMEM_TOTAL>>>(x, xb,   w1b, beff1, gamma1, beta1, out, midb);
    convw_kernel<<<1024, 256>>>(w2, gain3, w2b);
    beff_kernel<<<16, 1024>>>(w2, b2, nbias3, beff2);
    bt_gemm<true ><<<grid, block, SMEM_TOTAL>>>(x, midb, w2b, beff2, gamma3, beta3, out, midb);
}

// round 17
// speedup vs baseline: 1.0527x; 1.0527x over previous
#include <cuda_runtime.h>
#include <cuda_bf16.h>
#include <cstdint>

#define BATCH   16384
#define IN_SIZE 4096
#define NPART   8
#define DDIM    512

#define BM 128
#define BN 128
#define BK 64
#define THREADS 256
#define NCHUNK (DDIM / BK)       // 8
#define STAGES 3

#define TILE_BYTES   16384       // one 16KB operand tile (A: 128x64 bf16, B: 64x128 bf16)
#define STAGE_BYTES  (2 * TILE_BYTES)
#define SMEM_STAGE0  1024
#define SMEM_TOTAL   (SMEM_STAGE0 + STAGES * STAGE_BYTES)   // 99328

// Device-global scratch (allocation APIs forbidden).
// xb/midb: tile-major swizzled bf16 activations. A-tile index = (mt*8+p)*8+kc
// w1b/w2b: tile-major swizzled bf16 weights.     B-tile index = (p*4+nt)*8+kc
__device__ __align__(16) __nv_bfloat16 g_xb  [(size_t)BATCH * IN_SIZE];
__device__ __align__(16) __nv_bfloat16 g_midb[(size_t)BATCH * IN_SIZE];
__device__ __align__(16) __nv_bfloat16 g_w1b [(size_t)NPART * DDIM * DDIM];
__device__ __align__(16) __nv_bfloat16 g_w2b [(size_t)NPART * DDIM * DDIM];
__device__ float g_beff1[IN_SIZE];
__device__ float g_beff2[IN_SIZE];

// ---------------------------------------------------------------------------
#define MBARRIER_INIT(addr, cnt) \
    asm volatile("mbarrier.init.shared.b64 [%0], %1;" :: "r"(addr), "r"(cnt) : "memory")
#define MBARRIER_EXPECT_TX(addr, bytes) \
    asm volatile("mbarrier.arrive.expect_tx.shared.b64 _, [%0], %1;" \
                 :: "r"(addr), "r"(bytes) : "memory")
#define MBARRIER_ARRIVE(addr) \
    asm volatile("mbarrier.arrive.shared.b64 _, [%0];" :: "r"(addr) : "memory")
#define MBARRIER_WAIT_PARITY(mbar, par) do {                                   \
    uint32_t _m = (mbar); uint32_t _p = (par); uint32_t _done;                 \
    asm volatile("{\n\t.reg .pred p;\n\t"                                      \
        "mbarrier.try_wait.parity.acquire.cta.shared::cta.b64 p, [%1], %2;\n\t"\
        "selp.b32 %0, 1, 0, p;\n\t}"                                           \
        : "=r"(_done) : "r"(_m), "r"(_p) : "memory");                          \
    if (!_done) {                                                              \
        asm volatile("{\n\t.reg .pred P1;\n\t"                                 \
            "WAIT_LOOP_%=:\n\t"                                                \
            "mbarrier.try_wait.parity.acquire.cta.shared::cta.b64 P1, [%0], %1, 0x989680;\n\t" \
            "@P1 bra.uni WAIT_DONE_%=;\n\t"                                    \
            "bra.uni WAIT_LOOP_%=;\n\t"                                        \
            "WAIT_DONE_%=:\n\t}"                                               \
            :: "r"(_m), "r"(_p) : "memory");                                   \
    }                                                                          \
} while (0)

// Bulk async copy global->shared (UBLKCP). sm_90 baseline PTX (not 'a'-gated).
#define CP_BULK_G2S(dst, src, bytes, mbar) \
    asm volatile("cp.async.bulk.shared::cluster.global.mbarrier::complete_tx::bytes " \
                 "[%0], [%1], %2, [%3];" \
                 :: "r"(dst), "l"(src), "r"(bytes), "r"(mbar) : "memory")

__device__ __forceinline__ void ldsm_x4(uint32_t* r, uint32_t addr) {
    asm volatile("ldmatrix.sync.aligned.m8n8.x4.shared.b16 {%0,%1,%2,%3}, [%4];"
                 : "=r"(r[0]), "=r"(r[1]), "=r"(r[2]), "=r"(r[3]) : "r"(addr));
}
__device__ __forceinline__ void ldsm_x4_t(uint32_t* r, uint32_t addr) {
    asm volatile("ldmatrix.sync.aligned.m8n8.x4.trans.shared.b16 {%0,%1,%2,%3}, [%4];"
                 : "=r"(r[0]), "=r"(r[1]), "=r"(r[2]), "=r"(r[3]) : "r"(addr));
}
__device__ __forceinline__ void mma_bf16(float c[4], const uint32_t a[4],
                                         uint32_t b0, uint32_t b1) {
    asm volatile(
        "mma.sync.aligned.m16n8k16.row.col.f32.bf16.bf16.f32 "
        "{%0,%1,%2,%3}, {%4,%5,%6,%7}, {%8,%9}, {%0,%1,%2,%3};"
        : "+f"(c[0]), "+f"(c[1]), "+f"(c[2]), "+f"(c[3])
        : "r"(a[0]), "r"(a[1]), "r"(a[2]), "r"(a[3]), "r"(b0), "r"(b1));
}

// ---------------------------------------------------------------------------
// bias_eff[col] = bias[col] + nb * colsum(W)[col]  — coalesced.
__global__ void beff_kernel(const float* __restrict__ W,
                            const float* __restrict__ bias,
                            const float* __restrict__ nb,
                            float* __restrict__ beff) {
    __shared__ float part[4][256];
    const int p    = blockIdx.x >> 1;
    const int half = blockIdx.x & 1;
    const int c    = threadIdx.x & 255;
    const int ks   = threadIdx.x >> 8;
    const int col  = half * 256 + c;

    const float* Wp = W + (size_t)p * DDIM * DDIM + col;
    float sum = 0.f;
    const int k0 = ks * 128;
    #pragma unroll 8
    for (int k = k0; k < k0 + 128; k++) sum += Wp[(size_t)k * DDIM];
    part[ks][c] = sum;
    __syncthreads();
    if (ks == 0) {
        float s = part[0][c] + part[1][c] + part[2][c] + part[3][c];
        beff[p * DDIM + col] = bias[p * DDIM + col] + nb[0] * s;
    }
}

// W * gain -> bf16, tiled+swizzled. B tile for (p,nt,kc): 64 K-rows x 128 N-cols,
// stored as two 64x64 halves; off = h*8192 + kk*128 + ((nn*2) ^ ((kk&7)*16)).
__global__ void convw_kernel(const float* __restrict__ W,
                             const float* __restrict__ gain_p,
                             __nv_bfloat16* __restrict__ Wb) {
    const float gain = gain_p[0];
    int gid = blockIdx.x * blockDim.x + threadIdx.x;   // 8 elems each
    int n0  = (gid & 63) * 8;
    int k   = (gid >> 6) & 511;
    int p   = gid >> 15;

    const float* src = W + ((size_t)p * DDIM + k) * DDIM + n0;
    float4 v0 = *reinterpret_cast<const float4*>(src);
    float4 v1 = *reinterpret_cast<const float4*>(src + 4);
    __nv_bfloat162 o[4];
    o[0] = __floats2bfloat162_rn(v0.x * gain, v0.y * gain);
    o[1] = __floats2bfloat162_rn(v0.z * gain, v0.w * gain);
    o[2] = __floats2bfloat162_rn(v1.x * gain, v1.y * gain);
    o[3] = __floats2bfloat162_rn(v1.z * gain, v1.w * gain);

    int kc = k >> 6, kk = k & 63;
    int nt = n0 >> 7, h = (n0 >> 6) & 1, nn = n0 & 63;
    size_t tile = ((size_t)(p * 4 + nt) * NCHUNK + kc) * TILE_BYTES;
    uint32_t off = h * 8192 + kk * 128 + (uint32_t)((nn * 2) ^ ((kk & 7) * 16));
    *reinterpret_cast<uint4*>(reinterpret_cast<char*>(Wb) + tile + off) =
        *reinterpret_cast<uint4*>(o);
}

// x -> bf16, tiled+swizzled A tiles.
__global__ void convx_kernel(const float* __restrict__ X,
                             __nv_bfloat16* __restrict__ Xb) {
    int gid = blockIdx.x * blockDim.x + threadIdx.x;
    int c0  = (gid & 63) * 8;
    int prow = gid >> 6;
    int p   = prow & 7;
    int row = prow >> 3;

    const float* src = X + (size_t)row * IN_SIZE + p * DDIM + c0;
    float4 v0 = *reinterpret_cast<const float4*>(src);
    float4 v1 = *reinterpret_cast<const float4*>(src + 4);
    __nv_bfloat162 o[4];
    o[0] = __floats2bfloat162_rn(v0.x, v0.y);
    o[1] = __floats2bfloat162_rn(v0.z, v0.w);
    o[2] = __floats2bfloat162_rn(v1.x, v1.y);
    o[3] = __floats2bfloat162_rn(v1.z, v1.w);

    int mt = row >> 7, r = row & 127;
    int kc = c0 >> 6, c = c0 & 63;
    size_t tile = ((size_t)(mt * NPART + p) * NCHUNK + kc) * TILE_BYTES;
    uint32_t off = r * 128 + (uint32_t)((c * 2) ^ ((r & 7) * 16));
    *reinterpret_cast<uint4*>(reinterpret_cast<char*>(Xb) + tile + off) =
        *reinterpret_cast<uint4*>(o);
}

// ---------------------------------------------------------------------------
// One layer GEMM: Out = swish( A @ W_eff_p + beff, gamma, beta ) [+ X residual]
// Warp-decoupled 3-stage pipeline, producer at bottom (R14-proven, untouched).
template <bool SECOND>
__global__ __launch_bounds__(THREADS, 2)
void bt_gemm(const float* __restrict__ X,
             const __nv_bfloat16* __restrict__ Ain,   // tiled (xb or midb)
             const __nv_bfloat16* __restrict__ Wb,    // tiled weights
             const float* __restrict__ beff,
             const float* __restrict__ gamma,
             const float* __restrict__ beta,
             float* __restrict__ Out,
             __nv_bfloat16* __restrict__ MidOut) {    // tiled (layer1 output)
    extern __shared__ char smem[];
    const uint32_t sb = (uint32_t)__cvta_generic_to_shared(smem);

    const int tid  = threadIdx.x;
    const int warp = tid >> 5;
    const int lane = tid & 31;

    const int ng = blockIdx.x;            // 0..31  (partition*4 + n-tile)
    const int mt = blockIdx.y;            // 0..127
    const int p  = ng >> 2;
    const int nt = ng & 3;

    const int row0  = mt * BM;
    const int gcol0 = p * DDIM + nt * BN;

    // full[s] at sb + 8*s ; empty[s] at sb + 24 + 8*s
    if (tid == 0) {
        MBARRIER_INIT(sb + 0, 1);
        MBARRIER_INIT(sb + 8, 1);
        MBARRIER_INIT(sb + 16, 1);
        MBARRIER_INIT(sb + 24, 8);
        MBARRIER_INIT(sb + 32, 8);
        MBARRIER_INIT(sb + 40, 8);
    }
    __syncthreads();

    const char* Abase = reinterpret_cast<const char*>(Ain) +
                        ((size_t)(mt * NPART + p) * NCHUNK) * TILE_BYTES;
    const char* Bbase = reinterpret_cast<const char*>(Wb) +
                        ((size_t)(p * 4 + nt) * NCHUNK) * TILE_BYTES;

    auto issue = [&](int s, int kc) {
        uint32_t mb = sb + 8 * s;
        uint32_t a_st = sb + SMEM_STAGE0 + s * STAGE_BYTES;
        MBARRIER_EXPECT_TX(mb, STAGE_BYTES);
        CP_BULK_G2S(a_st, Abase + (size_t)kc * TILE_BYTES, TILE_BYTES, mb);
        CP_BULK_G2S(a_st + TILE_BYTES, Bbase + (size_t)kc * TILE_BYTES, TILE_BYTES, mb);
    };

    // Prologue: all 3 stages in flight.
    if (tid == 0) { issue(0, 0); issue(1, 1); issue(2, 2); }

    // Warp layout: 4 (M) x 2 (N); warp tile 32x64
    const int wm = (warp >> 1) * 32;
    const int wn = (warp & 1) * 64;
    const int bh = wn >> 6;

    const int a_row = wm + (lane & 15);
    const int a_cb  = (lane >> 4) * 16;
    const int b_row = lane & 15;
    const int b_nb  = (lane >> 4) * 16;

    float acc[2][8][4];
    #pragma unroll
    for (int i = 0; i < 2; i++)
        #pragma unroll
        for (int j = 0; j < 8; j++)
            #pragma unroll
            for (int k = 0; k < 4; k++) acc[i][j][k] = 0.0f;

    uint32_t af[2][2][4];   // [kk-parity][im][frag]
    uint32_t bb[2][4];      // [np-parity][frag]

    #pragma unroll
    for (int kc = 0; kc < NCHUNK; kc++) {
        const int s = kc % STAGES;

        MBARRIER_WAIT_PARITY(sb + 8 * s, (kc / 3) & 1);

        const uint32_t a_st = sb + SMEM_STAGE0 + s * STAGE_BYTES;
        const uint32_t b_st = a_st + TILE_BYTES + bh * 8192;

        auto a_addr = [&](int kk, int im) -> uint32_t {
            int r = a_row + im * 16;
            return a_st + r * 128 + (uint32_t)((kk * 2 + a_cb) ^ ((r & 7) * 16));
        };
        auto b_addr = [&](int kk, int np) -> uint32_t {
            int r = kk + b_row;
            return b_st + r * 128 + (uint32_t)((np * 32 + b_nb) ^ ((r & 7) * 16));
        };

        ldsm_x4(af[0][0], a_addr(0, 0));
        ldsm_x4(af[0][1], a_addr(0, 1));
        ldsm_x4_t(bb[0], b_addr(0, 0));

        #pragma unroll
        for (int ki = 0; ki < 4; ki++) {
            const int kk = ki * 16;
            const int pa = ki & 1;
            #pragma unroll
            for (int np = 0; np < 4; np++) {
                const int cb = np & 1;
                if (np < 3) {
                    ldsm_x4_t(bb[cb ^ 1], b_addr(kk, np + 1));
                } else if (ki < 3) {
                    ldsm_x4_t(bb[cb ^ 1], b_addr(kk + 16, 0));
                    ldsm_x4(af[pa ^ 1][0], a_addr(kk + 16, 0));
                    ldsm_x4(af[pa ^ 1][1], a_addr(kk + 16, 1));
                }
                mma_bf16(acc[0][np * 2 + 0], af[pa][0], bb[cb][0], bb[cb][1]);
                mma_bf16(acc[0][np * 2 + 1], af[pa][0], bb[cb][2], bb[cb][3]);
                mma_bf16(acc[1][np * 2 + 0], af[pa][1], bb[cb][0], bb[cb][1]);
                mma_bf16(acc[1][np * 2 + 1], af[pa][1], bb[cb][2], bb[cb][3]);
            }
        }

        // Consumer arrival: this warp is done reading stage s.
        if (kc + STAGES < NCHUNK && lane == 0) MBARRIER_ARRIVE(sb + 24 + 8 * s);

        // Producer (bottom): reissue this stage for chunk kc+3 once all 8
        // warps drained chunk kc (warp 0 already arrived above).
        if (tid == 0 && kc + STAGES < NCHUNK) {
            MBARRIER_WAIT_PARITY(sb + 24 + 8 * s, (kc / 3) & 1);
            issue(s, kc + STAGES);
        }
    }

    // ---- epilogue: v = acc + beff; parametric swish; (+residual)
    const int g  = lane >> 2;
    const int t2 = (lane & 3) << 1;
    #pragma unroll
    for (int im = 0; im < 2; im++) {
        #pragma unroll
        for (int n_ = 0; n_ < 8; n_++) {
            const int rowA = row0 + wm + im * 16 + g;
            const int col  = gcol0 + wn + n_ * 8 + t2;
            const float be0 = beff[col],  be1 = beff[col + 1];
            const float gm0 = gamma[col], gm1 = gamma[col + 1];
            const float bt0 = beta[col],  bt1 = beta[col + 1];
            #pragma unroll
            for (int h = 0; h < 2; h++) {
                const int rg = rowA + h * 8;
                float v0 = acc[im][n_][h * 2 + 0] + be0;
                float v1 = acc[im][n_][h * 2 + 1] + be1;
                const float s0 = 1.0f / (1.0f + __expf(-bt0 * v0));
                const float s1 = 1.0f / (1.0f + __expf(-bt1 * v1));
                float o0 = (gm0 + s0 * (1.0f - gm0)) * v0;
                float o1 = (gm1 + s1 * (1.0f - gm1)) * v1;
                if (SECOND) {
                    const float2 rx = *reinterpret_cast<const float2*>(
                        &X[(size_t)rg * IN_SIZE + col]);
                    *reinterpret_cast<float2*>(&Out[(size_t)rg * IN_SIZE + col]) =
                        make_float2(o0 + rx.x, o1 + rx.y);
                } else {
                    int r  = rg & 127;
                    int k2 = col & 511;
                    int kc2 = k2 >> 6, cc = k2 & 63;
                    size_t tile = ((size_t)(mt * NPART + p) * NCHUNK + kc2) *
                                  TILE_BYTES;
                    uint32_t off = r * 128 +
                                   (uint32_t)((cc * 2) ^ ((r & 7) * 16));
                    *reinterpret_cast<__nv_bfloat162*>(
                        reinterpret_cast<char*>(MidOut) + tile + off) =
                        __floats2bfloat162_rn(o0, o1);
                }
            }
        }
    }
}

// ---------------------------------------------------------------------------
extern "C" void kernel_launch(void* const* d_in, const int* in_sizes, int n_in,
                              void* d_out, int out_size) {
    (void)in_sizes; (void)n_in; (void)out_size;
    const float* x      = (const float*)d_in[0];
    const float* w1     = (const float*)d_in[1];
    const float* b1     = (const float*)d_in[2];
    const float* w2     = (const float*)d_in[3];
    const float* b2     = (const float*)d_in[4];
    const float* gamma1 = (const float*)d_in[5];
    const float* beta1  = (const float*)d_in[6];
    const float* gamma3 = (const float*)d_in[7];
    const float* beta3  = (const float*)d_in[8];
    const float* gain1  = (const float*)d_in[9];
    const float* nbias1 = (const float*)d_in[10];
    const float* gain3  = (const float*)d_in[11];
    const float* nbias3 = (const float*)d_in[12];
    float* out = (float*)d_out;

    __nv_bfloat16 *xb, *midb, *w1b, *w2b;
    float *beff1, *beff2;
    cudaGetSymbolAddress((void**)&xb,    g_xb);
    cudaGetSymbolAddress((void**)&midb,  g_midb);
    cudaGetSymbolAddress((void**)&w1b,   g_w1b);
    cudaGetSymbolAddress((void**)&w2b,   g_w2b);
    cudaGetSymbolAddress((void**)&beff1, g_beff1);
    cudaGetSymbolAddress((void**)&beff2, g_beff2);

    // One-time host-side setup (no device allocation: streams/events are
    // host objects; func attrs are metadata). Work per call is identical.
    static cudaStream_t sW = nullptr;
    static cudaEvent_t  eFork = nullptr, eL1 = nullptr, eL2 = nullptr;
    if (sW == nullptr) {
        cudaStreamCreateWithFlags(&sW, cudaStreamNonBlocking);
        cudaEventCreateWithFlags(&eFork, cudaEventDisableTiming);
        cudaEventCreateWithFlags(&eL1,   cudaEventDisableTiming);
        cudaEventCreateWithFlags(&eL2,   cudaEventDisableTiming);
        cudaFuncSetAttribute(bt_gemm<false>,
                             cudaFuncAttributeMaxDynamicSharedMemorySize, SMEM_TOTAL);
        cudaFuncSetAttribute(bt_gemm<true>,
                             cudaFuncAttributeMaxDynamicSharedMemorySize, SMEM_TOTAL);
    }

    dim3 grid(32, 128);
    dim3 block(THREADS);

    // Launch DAG (capturable fork-join):
    //   main: convx ─────────────┬─ gemm1 ─┬─ gemm2
    //   sW:   convw1→beff1 ──────┘         │
    //         convw2→beff2 ───────────────-┘
    cudaEventRecord(eFork, 0);
    cudaStreamWaitEvent(sW, eFork, 0);

    convw_kernel<<<1024, 256, 0, sW>>>(w1, gain1, w1b);
    beff_kernel<<<16, 1024, 0, sW>>>(w1, b1, nbias1, beff1);
    cudaEventRecord(eL1, sW);
    convw_kernel<<<1024, 256, 0, sW>>>(w2, gain3, w2b);
    beff_kernel<<<16, 1024, 0, sW>>>(w2, b2, nbias3, beff2);
    cudaEventRecord(eL2, sW);

    convx_kernel<<<32768, 256>>>(x, xb);

    cudaStreamWaitEvent(0, eL1, 0);
    bt_gemm<false><<<grid, block, SMEM_TOTAL>>>(x, xb,   w1b, beff1, gamma1, beta1, out, midb);
    cudaStreamWaitEvent(0, eL2, 0);
    bt_gemm<true ><<<grid, block, SMEM_TOTAL>>>(x, midb, w2b, beff2, gamma3, beta3, out, midb);
}